// round 4
// baseline (speedup 1.0000x reference)
#include <cuda_runtime.h>
#include <cuda_bf16.h>
#include <cstddef>

// Problem constants (fixed by the dataset)
#define NN 64000
#define EE 1048576
#define NG 64
#define NBN 1000
#define F_IN 128
#define H1 256
#define H2 256
#define H3 128
#define OUTD 64

// -------------------- scratch (device globals; no allocs) --------------------
__device__ __align__(16) float g_bufA[(size_t)NN * 256];
__device__ __align__(16) float g_bufB[(size_t)NN * 256];
__device__ int   g_counts[NN];
__device__ int   g_offsets[NN + 1];
__device__ int   g_fill[NN];
__device__ int   g_srcSorted[EE];
__device__ float g_dinv[NN];
__device__ int   g_isI64;

// buffer selector (device-side only)
__device__ __forceinline__ float* bufsel(int s) { return s == 0 ? g_bufA : g_bufB; }

// fetch an edge-index element robustly against int32-vs-int64 storage
__device__ __forceinline__ int ei_at(const void* ei, size_t idx) {
    if (g_isI64) return (int)((const long long*)ei)[idx];
    return ((const int*)ei)[idx];
}

// -------------------- dtype detection --------------------
// int64 node ids < 64000 -> every odd 32-bit word is 0.
// int32 random node ids -> 32 consecutive zeros at odd positions is impossible.
__global__ void detect_kernel(const void* ei) {
    const unsigned int* w = (const unsigned int*)ei;
    int is64 = 1;
    #pragma unroll
    for (int i = 0; i < 32; i++)
        if (w[2 * i + 1] != 0u) is64 = 0;
    g_isI64 = is64;
}

// -------------------- preprocessing --------------------
__global__ void zero_kernel() {
    int i = blockIdx.x * blockDim.x + threadIdx.x;
    if (i < NN) { g_counts[i] = 0; g_fill[i] = 0; }
}

__global__ void hist_kernel(const void* __restrict__ ei) {
    int e = blockIdx.x * blockDim.x + threadIdx.x;
    if (e < EE) {
        int d = ei_at(ei, (size_t)EE + e);
        atomicAdd(&g_counts[d], 1);
    }
}

// single-block exclusive scan over counts -> offsets; also dinv = rsqrt(deg+1)
__global__ void scan_kernel() {
    __shared__ int sh[1024];
    __shared__ int carrySh;
    int tid = threadIdx.x;
    if (tid == 0) carrySh = 0;
    __syncthreads();
    for (int base = 0; base < NN; base += 1024) {
        int i = base + tid;
        int c = (i < NN) ? g_counts[i] : 0;
        sh[tid] = c;
        __syncthreads();
        #pragma unroll
        for (int off = 1; off < 1024; off <<= 1) {
            int v = (tid >= off) ? sh[tid - off] : 0;
            __syncthreads();
            sh[tid] += v;
            __syncthreads();
        }
        int incl = sh[tid];
        int carry = carrySh;
        if (i < NN) {
            g_offsets[i] = carry + incl - c;
            g_dinv[i] = rsqrtf((float)(c + 1));
        }
        __syncthreads();
        if (tid == 0) carrySh = carry + sh[1023];
        __syncthreads();
    }
    if (tid == 0) g_offsets[NN] = carrySh;
}

__global__ void scatter_kernel(const void* __restrict__ ei) {
    int e = blockIdx.x * blockDim.x + threadIdx.x;
    if (e < EE) {
        int d = ei_at(ei, (size_t)EE + e);
        int s = ei_at(ei, (size_t)e);
        int pos = g_offsets[d] + atomicAdd(&g_fill[d], 1);
        g_srcSorted[pos] = s;
    }
}

// -------------------- dense GEMM: C[M,NOUT] = A[M,K] @ B[K,NOUT] --------------------
// 64x64 tile, BK=16, 256 threads, 4x4 register blocking.
// ASEL: -1 = use Aext param, 0 = g_bufA, 1 = g_bufB. CSEL: 0 = g_bufA, 1 = g_bufB.
template <int K, int NOUT, int ASEL, int CSEL>
__global__ void gemm_kernel(const float* __restrict__ Aext,
                            const float* __restrict__ B) {
    const float* __restrict__ A = (ASEL < 0) ? Aext : (const float*)bufsel(ASEL);
    float* __restrict__ C = bufsel(CSEL);

    __shared__ float As[64][17];
    __shared__ float Bs[16][64];
    const int m0 = blockIdx.y * 64;
    const int n0 = blockIdx.x * 64;
    const int t = threadIdx.x;
    const int r = t / 16, c = t % 16;

    float acc[4][4];
    #pragma unroll
    for (int i = 0; i < 4; i++)
        #pragma unroll
        for (int j = 0; j < 4; j++) acc[i][j] = 0.0f;

    const int arow = t >> 2, aq = t & 3;
    const int bkr  = t >> 4, bq = t & 15;

    for (int k0 = 0; k0 < K; k0 += 16) {
        float4 av = *(const float4*)(A + (size_t)(m0 + arow) * K + k0 + 4 * aq);
        As[arow][4 * aq + 0] = av.x;
        As[arow][4 * aq + 1] = av.y;
        As[arow][4 * aq + 2] = av.z;
        As[arow][4 * aq + 3] = av.w;
        float4 bv = *(const float4*)(B + (size_t)(k0 + bkr) * NOUT + n0 + 4 * bq);
        *(float4*)&Bs[bkr][4 * bq] = bv;
        __syncthreads();

        #pragma unroll
        for (int k = 0; k < 16; k++) {
            float4 b4 = *(const float4*)&Bs[k][4 * c];
            float a0 = As[4 * r + 0][k];
            float a1 = As[4 * r + 1][k];
            float a2 = As[4 * r + 2][k];
            float a3 = As[4 * r + 3][k];
            acc[0][0] += a0 * b4.x; acc[0][1] += a0 * b4.y; acc[0][2] += a0 * b4.z; acc[0][3] += a0 * b4.w;
            acc[1][0] += a1 * b4.x; acc[1][1] += a1 * b4.y; acc[1][2] += a1 * b4.z; acc[1][3] += a1 * b4.w;
            acc[2][0] += a2 * b4.x; acc[2][1] += a2 * b4.y; acc[2][2] += a2 * b4.z; acc[2][3] += a2 * b4.w;
            acc[3][0] += a3 * b4.x; acc[3][1] += a3 * b4.y; acc[3][2] += a3 * b4.z; acc[3][3] += a3 * b4.w;
        }
        __syncthreads();
    }

    #pragma unroll
    for (int i = 0; i < 4; i++) {
        float4 v = make_float4(acc[i][0], acc[i][1], acc[i][2], acc[i][3]);
        *(float4*)(C + (size_t)(m0 + 4 * r + i) * NOUT + n0 + 4 * c) = v;
    }
}

// -------------------- aggregation: warp per node, gather-only, tanh fused --------------------
template <int H, int SRCSEL, int DSTSEL>
__global__ void agg_kernel(const float* __restrict__ bias) {
    const float* __restrict__ hl = bufsel(SRCSEL);
    float* __restrict__ outp = bufsel(DSTSEL);

    int gw = (blockIdx.x * blockDim.x + threadIdx.x) >> 5;
    int lane = threadIdx.x & 31;
    if (gw >= NN) return;
    const int n = gw;
    const float dd = g_dinv[n];
    const float w0 = dd * dd;

    const float4* selfp = (const float4*)(hl + (size_t)n * H);
    float4 acc0 = selfp[lane];
    acc0.x *= w0; acc0.y *= w0; acc0.z *= w0; acc0.w *= w0;
    float4 acc1;
    if (H == 256) {
        acc1 = selfp[lane + 32];
        acc1.x *= w0; acc1.y *= w0; acc1.z *= w0; acc1.w *= w0;
    }

    const int e0 = g_offsets[n], e1 = g_offsets[n + 1];
    for (int e = e0; e < e1; e++) {
        int s = g_srcSorted[e];
        float w = dd * g_dinv[s];
        const float4* p = (const float4*)(hl + (size_t)s * H);
        float4 v = p[lane];
        acc0.x += w * v.x; acc0.y += w * v.y; acc0.z += w * v.z; acc0.w += w * v.w;
        if (H == 256) {
            float4 v1 = p[lane + 32];
            acc1.x += w * v1.x; acc1.y += w * v1.y; acc1.z += w * v1.z; acc1.w += w * v1.w;
        }
    }

    const float4* b4 = (const float4*)bias;
    float4 bb = b4[lane];
    float4 o0;
    o0.x = tanhf(acc0.x + bb.x);
    o0.y = tanhf(acc0.y + bb.y);
    o0.z = tanhf(acc0.z + bb.z);
    o0.w = tanhf(acc0.w + bb.w);
    float4* op = (float4*)(outp + (size_t)n * H);
    op[lane] = o0;
    if (H == 256) {
        float4 bb1 = b4[lane + 32];
        float4 o1;
        o1.x = tanhf(acc1.x + bb1.x);
        o1.y = tanhf(acc1.y + bb1.y);
        o1.z = tanhf(acc1.z + bb1.z);
        o1.w = tanhf(acc1.w + bb1.w);
        op[lane + 32] = o1;
    }
}

// -------------------- final FC: out[64,64] = h3.reshape(64,128000) @ Wfc + bfc --------------------
__global__ void fc_init(const float* __restrict__ bfc, float* __restrict__ out) {
    int i = blockIdx.x * blockDim.x + threadIdx.x;
    if (i < NG * OUTD) out[i] = bfc[i & 63];
}

#define FC_KCH 1024
__global__ void fc_kernel(const float* __restrict__ Wfc,
                          float* __restrict__ out) {
    const float* __restrict__ h3 = g_bufA;  // h3 lives in bufA after layer 3
    __shared__ float Ws[16][64];
    __shared__ float Hs[64][17];
    const int t = threadIdx.x;
    const int tg = t & 15;   // graph group (4 graphs each)
    const int to = t >> 4;   // out group (4 outs each)
    float acc[4][4];
    #pragma unroll
    for (int i = 0; i < 4; i++)
        #pragma unroll
        for (int j = 0; j < 4; j++) acc[i][j] = 0.0f;

    const int kbase = blockIdx.x * FC_KCH;
    for (int kk0 = 0; kk0 < FC_KCH; kk0 += 16) {
        const int k0 = kbase + kk0;
        #pragma unroll
        for (int rr = 0; rr < 4; rr++) {
            int idx = t + rr * 256;
            int kr = idx >> 6, nn = idx & 63;
            Ws[kr][nn] = Wfc[(size_t)(k0 + kr) * OUTD + nn];
        }
        #pragma unroll
        for (int rr = 0; rr < 4; rr++) {
            int idx = t + rr * 256;
            int g = idx >> 4, kk = idx & 15;
            Hs[g][kk] = h3[(size_t)g * 128000 + k0 + kk];
        }
        __syncthreads();
        #pragma unroll
        for (int kk = 0; kk < 16; kk++) {
            float hv[4], wv[4];
            #pragma unroll
            for (int i = 0; i < 4; i++) hv[i] = Hs[4 * tg + i][kk];
            #pragma unroll
            for (int j = 0; j < 4; j++) wv[j] = Ws[kk][4 * to + j];
            #pragma unroll
            for (int i = 0; i < 4; i++)
                #pragma unroll
                for (int j = 0; j < 4; j++) acc[i][j] += hv[i] * wv[j];
        }
        __syncthreads();
    }
    #pragma unroll
    for (int i = 0; i < 4; i++)
        #pragma unroll
        for (int j = 0; j < 4; j++)
            atomicAdd(&out[(4 * tg + i) * OUTD + 4 * to + j], acc[i][j]);
}

// -------------------- launch --------------------
extern "C" void kernel_launch(void* const* d_in, const int* in_sizes, int n_in,
                              void* d_out, int out_size) {
    const float* x   = (const float*)d_in[0];
    const void*  ei  = d_in[1];              // int32 or int64 -> detected on device
    // d_in[2] = batch (unused: sorted equal-size graphs -> implicit)
    const float* W1  = (const float*)d_in[3];
    const float* b1  = (const float*)d_in[4];
    const float* W2  = (const float*)d_in[5];
    const float* b2  = (const float*)d_in[6];
    const float* W3  = (const float*)d_in[7];
    const float* b3  = (const float*)d_in[8];
    const float* Wfc = (const float*)d_in[9];
    const float* bfc = (const float*)d_in[10];
    float* out = (float*)d_out;

    // preprocessing: dtype detect, degree, offsets, dinv, dst-sorted edge list
    detect_kernel<<<1, 1>>>(ei);
    zero_kernel<<<(NN + 255) / 256, 256>>>();
    hist_kernel<<<EE / 256, 256>>>(ei);
    scan_kernel<<<1, 1024>>>();
    scatter_kernel<<<EE / 256, 256>>>(ei);

    const int aggBlocks = (NN * 32) / 256;  // warp per node

    // layer 1: bufB = x @ W1 ; bufA = tanh(agg(bufB) + b1)
    gemm_kernel<F_IN, H1, -1, 1><<<dim3(H1 / 64, NN / 64), 256>>>(x, W1);
    agg_kernel<H1, 1, 0><<<aggBlocks, 256>>>(b1);

    // layer 2: bufB = bufA @ W2 ; bufA = tanh(agg(bufB) + b2)
    gemm_kernel<H1, H2, 0, 1><<<dim3(H2 / 64, NN / 64), 256>>>(nullptr, W2);
    agg_kernel<H2, 1, 0><<<aggBlocks, 256>>>(b2);

    // layer 3: bufB = bufA @ W3 ; bufA = tanh(agg(bufB) + b3)
    gemm_kernel<H2, H3, 0, 1><<<dim3(H3 / 64, NN / 64), 256>>>(nullptr, W3);
    agg_kernel<H3, 1, 0><<<aggBlocks, 256>>>(b3);

    // final FC with split-K atomics
    fc_init<<<(NG * OUTD + 255) / 256, 256>>>(bfc, out);
    fc_kernel<<<128000 / FC_KCH, 256>>>(Wfc, out);
}

// round 5
// speedup vs baseline: 1.1887x; 1.1887x over previous
#include <cuda_runtime.h>
#include <cuda_bf16.h>
#include <cstddef>

// Problem constants (fixed by the dataset)
#define NN 64000
#define EE 1048576
#define NG 64
#define NBN 1000
#define F_IN 128
#define H1 256
#define H2 256
#define H3 128
#define OUTD 64

// -------------------- scratch (device globals; no allocs) --------------------
__device__ __align__(16) float g_bufA[(size_t)NN * 256];
__device__ __align__(16) float g_bufB[(size_t)NN * 256];
__device__ int   g_counts[NN];
__device__ int   g_offsets[NN + 1];
__device__ int   g_fill[NN];
__device__ int   g_srcSorted[EE];
__device__ float g_dinv[NN];
__device__ int   g_isI64;
__device__ int   g_bsum[256];
__device__ int   g_boff[256];

__device__ __forceinline__ float* bufsel(int s) { return s == 0 ? g_bufA : g_bufB; }

__device__ __forceinline__ int ei_at(const void* ei, size_t idx) {
    if (g_isI64) return (int)((const long long*)ei)[idx];
    return ((const int*)ei)[idx];
}

// packed f32x2 helpers (FFMA2 only reachable via PTX)
__device__ __forceinline__ unsigned long long pack2(float x, float y) {
    unsigned long long r;
    asm("mov.b64 %0, {%1, %2};" : "=l"(r) : "f"(x), "f"(y));
    return r;
}
__device__ __forceinline__ void unpack2(unsigned long long p, float& x, float& y) {
    asm("mov.b64 {%0, %1}, %2;" : "=f"(x), "=f"(y) : "l"(p));
}
#define FFMA2(acc, ap, bp) \
    asm("fma.rn.f32x2 %0, %1, %2, %0;" : "+l"(acc) : "l"(ap), "l"(bp))

// -------------------- dtype detection --------------------
__global__ void detect_kernel(const void* ei) {
    const unsigned int* w = (const unsigned int*)ei;
    int is64 = 1;
    #pragma unroll
    for (int i = 0; i < 32; i++)
        if (w[2 * i + 1] != 0u) is64 = 0;
    g_isI64 = is64;
}

// -------------------- preprocessing --------------------
__global__ void zero_kernel() {
    int i = blockIdx.x * blockDim.x + threadIdx.x;
    if (i < NN) g_fill[i] = 0;
    if (i < NN) g_counts[i] = 0;
}

__global__ void hist_kernel(const void* __restrict__ ei) {
    int e = blockIdx.x * blockDim.x + threadIdx.x;
    if (e < EE) {
        int d = ei_at(ei, (size_t)EE + e);
        atomicAdd(&g_counts[d], 1);
    }
}

// two-level scan: (1) per-block reduce, (2) scan partials, (3) per-block scan
__global__ void reduce_kernel() {
    int b = blockIdx.x;
    int v = g_counts[b * 256 + threadIdx.x];
    #pragma unroll
    for (int o = 16; o; o >>= 1) v += __shfl_down_sync(0xffffffffu, v, o);
    __shared__ int ws[8];
    if ((threadIdx.x & 31) == 0) ws[threadIdx.x >> 5] = v;
    __syncthreads();
    if (threadIdx.x == 0) {
        int s = 0;
        #pragma unroll
        for (int i = 0; i < 8; i++) s += ws[i];
        g_bsum[b] = s;
    }
}

__global__ void scanpart_kernel() {  // 1 block, 256 threads over 250 partials
    int t = threadIdx.x;
    int v = (t < NN / 256) ? g_bsum[t] : 0;
    int lane = t & 31, w = t >> 5;
    int x = v;
    #pragma unroll
    for (int o = 1; o < 32; o <<= 1) {
        int y = __shfl_up_sync(0xffffffffu, x, o);
        if (lane >= o) x += y;
    }
    __shared__ int ws[8], wso[8];
    if (lane == 31) ws[w] = x;
    __syncthreads();
    if (t < 8) {
        int s = 0;
        for (int i = 0; i < t; i++) s += ws[i];
        wso[t] = s;
    }
    __syncthreads();
    int incl = x + wso[w];
    if (t < NN / 256) g_boff[t] = incl - v;  // exclusive
    if (t == 255) g_offsets[NN] = incl;      // grand total
}

__global__ void blockscan_kernel() {
    int b = blockIdx.x, t = threadIdx.x, i = b * 256 + t;
    int c = g_counts[i];
    int lane = t & 31, w = t >> 5;
    int x = c;
    #pragma unroll
    for (int o = 1; o < 32; o <<= 1) {
        int y = __shfl_up_sync(0xffffffffu, x, o);
        if (lane >= o) x += y;
    }
    __shared__ int ws[8], wso[8];
    if (lane == 31) ws[w] = x;
    __syncthreads();
    if (t < 8) {
        int s = 0;
        for (int j = 0; j < t; j++) s += ws[j];
        wso[t] = s;
    }
    __syncthreads();
    g_offsets[i] = x - c + wso[w] + g_boff[b];
    g_dinv[i] = rsqrtf((float)(c + 1));
}

__global__ void scatter_kernel(const void* __restrict__ ei) {
    int e = blockIdx.x * blockDim.x + threadIdx.x;
    if (e < EE) {
        int d = ei_at(ei, (size_t)EE + e);
        int s = ei_at(ei, (size_t)e);
        int pos = g_offsets[d] + atomicAdd(&g_fill[d], 1);
        g_srcSorted[pos] = s;
    }
}

// -------------------- dense GEMM: C[M,NOUT] = A[M,K] @ B[K,NOUT] --------------------
// 128x128 tile, BK=16, 256 threads, 8x8 per-thread blocking, packed f32x2 FFMA.
// ASEL: -1 = Aext param, 0 = g_bufA, 1 = g_bufB. CSEL: 0 = g_bufA, 1 = g_bufB.
#define ASTRIDE 132
template <int K, int NOUT, int ASEL, int CSEL>
__global__ void __launch_bounds__(256, 2)
gemm_kernel(const float* __restrict__ Aext, const float* __restrict__ B) {
    const float* __restrict__ A = (ASEL < 0) ? Aext : (const float*)bufsel(ASEL);
    float* __restrict__ C = bufsel(CSEL);

    __shared__ float AsT[16][ASTRIDE];  // k-major transposed A tile
    __shared__ float Bs[16][128];

    const int m0 = blockIdx.y * 128;
    const int n0 = blockIdx.x * 128;
    const int t = threadIdx.x;
    const int r = t >> 4;   // 0..15 -> rows 8r..8r+7
    const int c = t & 15;   // 0..15 -> cols 8c..8c+7

    unsigned long long acc2[8][4];
    #pragma unroll
    for (int i = 0; i < 8; i++)
        #pragma unroll
        for (int j = 0; j < 4; j++) acc2[i][j] = 0ull;

    for (int k0 = 0; k0 < K; k0 += 16) {
        // load A tile 128x16 and transpose into AsT[k][m]
        #pragma unroll
        for (int i = 0; i < 2; i++) {
            int idx = t + i * 256;
            int row = idx >> 2, kq = idx & 3;
            float4 av = *(const float4*)(A + (size_t)(m0 + row) * K + k0 + 4 * kq);
            AsT[4 * kq + 0][row] = av.x;
            AsT[4 * kq + 1][row] = av.y;
            AsT[4 * kq + 2][row] = av.z;
            AsT[4 * kq + 3][row] = av.w;
        }
        // load B tile 16x128
        #pragma unroll
        for (int i = 0; i < 2; i++) {
            int idx = t + i * 256;
            int kr = idx >> 5, q = idx & 31;
            *(float4*)&Bs[kr][4 * q] =
                *(const float4*)(B + (size_t)(k0 + kr) * NOUT + n0 + 4 * q);
        }
        __syncthreads();

        #pragma unroll
        for (int k = 0; k < 16; k++) {
            float4 a0 = *(const float4*)&AsT[k][8 * r];
            float4 a1 = *(const float4*)&AsT[k][8 * r + 4];
            float4 b0 = *(const float4*)&Bs[k][8 * c];
            float4 b1 = *(const float4*)&Bs[k][8 * c + 4];
            unsigned long long bp[4];
            bp[0] = pack2(b0.x, b0.y);
            bp[1] = pack2(b0.z, b0.w);
            bp[2] = pack2(b1.x, b1.y);
            bp[3] = pack2(b1.z, b1.w);
            float ar[8] = {a0.x, a0.y, a0.z, a0.w, a1.x, a1.y, a1.z, a1.w};
            #pragma unroll
            for (int i = 0; i < 8; i++) {
                unsigned long long ap = pack2(ar[i], ar[i]);
                FFMA2(acc2[i][0], ap, bp[0]);
                FFMA2(acc2[i][1], ap, bp[1]);
                FFMA2(acc2[i][2], ap, bp[2]);
                FFMA2(acc2[i][3], ap, bp[3]);
            }
        }
        __syncthreads();
    }

    #pragma unroll
    for (int i = 0; i < 8; i++) {
        float v0, v1, v2, v3, v4, v5, v6, v7;
        unpack2(acc2[i][0], v0, v1);
        unpack2(acc2[i][1], v2, v3);
        unpack2(acc2[i][2], v4, v5);
        unpack2(acc2[i][3], v6, v7);
        float* cp = C + (size_t)(m0 + 8 * r + i) * NOUT + n0 + 8 * c;
        *(float4*)cp = make_float4(v0, v1, v2, v3);
        *(float4*)(cp + 4) = make_float4(v4, v5, v6, v7);
    }
}

// -------------------- aggregation: warp per node, gather-only, tanh fused --------------------
template <int H, int SRCSEL, int DSTSEL>
__global__ void agg_kernel(const float* __restrict__ bias) {
    const float* __restrict__ hl = bufsel(SRCSEL);
    float* __restrict__ outp = bufsel(DSTSEL);

    int gw = (blockIdx.x * blockDim.x + threadIdx.x) >> 5;
    int lane = threadIdx.x & 31;
    if (gw >= NN) return;
    const int n = gw;
    const float dd = g_dinv[n];
    const float w0 = dd * dd;

    const float4* selfp = (const float4*)(hl + (size_t)n * H);
    float4 acc0 = selfp[lane];
    acc0.x *= w0; acc0.y *= w0; acc0.z *= w0; acc0.w *= w0;
    float4 acc1;
    if (H == 256) {
        acc1 = selfp[lane + 32];
        acc1.x *= w0; acc1.y *= w0; acc1.z *= w0; acc1.w *= w0;
    }

    const int e0 = g_offsets[n], e1 = g_offsets[n + 1];
    for (int e = e0; e < e1; e++) {
        int s = g_srcSorted[e];
        float w = dd * g_dinv[s];
        const float4* p = (const float4*)(hl + (size_t)s * H);
        float4 v = p[lane];
        acc0.x += w * v.x; acc0.y += w * v.y; acc0.z += w * v.z; acc0.w += w * v.w;
        if (H == 256) {
            float4 v1 = p[lane + 32];
            acc1.x += w * v1.x; acc1.y += w * v1.y; acc1.z += w * v1.z; acc1.w += w * v1.w;
        }
    }

    const float4* b4 = (const float4*)bias;
    float4 bb = b4[lane];
    float4 o0;
    o0.x = tanhf(acc0.x + bb.x);
    o0.y = tanhf(acc0.y + bb.y);
    o0.z = tanhf(acc0.z + bb.z);
    o0.w = tanhf(acc0.w + bb.w);
    float4* op = (float4*)(outp + (size_t)n * H);
    op[lane] = o0;
    if (H == 256) {
        float4 bb1 = b4[lane + 32];
        float4 o1;
        o1.x = tanhf(acc1.x + bb1.x);
        o1.y = tanhf(acc1.y + bb1.y);
        o1.z = tanhf(acc1.z + bb1.z);
        o1.w = tanhf(acc1.w + bb1.w);
        op[lane + 32] = o1;
    }
}

// -------------------- final FC: out[64,64] = h3.reshape(64,128000) @ Wfc + bfc ------
__global__ void fc_init(const float* __restrict__ bfc, float* __restrict__ out) {
    int i = blockIdx.x * blockDim.x + threadIdx.x;
    if (i < NG * OUTD) out[i] = bfc[i & 63];
}

#define FC_KCH 1024
__global__ void fc_kernel(const float* __restrict__ Wfc,
                          float* __restrict__ out) {
    const float* __restrict__ h3 = g_bufA;  // h3 lives in bufA after layer 3
    __shared__ float Ws[16][64];
    __shared__ float Hs[64][17];
    const int t = threadIdx.x;
    const int tg = t & 15;
    const int to = t >> 4;
    float acc[4][4];
    #pragma unroll
    for (int i = 0; i < 4; i++)
        #pragma unroll
        for (int j = 0; j < 4; j++) acc[i][j] = 0.0f;

    const int kbase = blockIdx.x * FC_KCH;
    for (int kk0 = 0; kk0 < FC_KCH; kk0 += 16) {
        const int k0 = kbase + kk0;
        #pragma unroll
        for (int rr = 0; rr < 4; rr++) {
            int idx = t + rr * 256;
            int kr = idx >> 6, nn = idx & 63;
            Ws[kr][nn] = Wfc[(size_t)(k0 + kr) * OUTD + nn];
        }
        #pragma unroll
        for (int rr = 0; rr < 4; rr++) {
            int idx = t + rr * 256;
            int g = idx >> 4, kk = idx & 15;
            Hs[g][kk] = h3[(size_t)g * 128000 + k0 + kk];
        }
        __syncthreads();
        #pragma unroll
        for (int kk = 0; kk < 16; kk++) {
            float hv[4], wv[4];
            #pragma unroll
            for (int i = 0; i < 4; i++) hv[i] = Hs[4 * tg + i][kk];
            #pragma unroll
            for (int j = 0; j < 4; j++) wv[j] = Ws[kk][4 * to + j];
            #pragma unroll
            for (int i = 0; i < 4; i++)
                #pragma unroll
                for (int j = 0; j < 4; j++) acc[i][j] += hv[i] * wv[j];
        }
        __syncthreads();
    }
    #pragma unroll
    for (int i = 0; i < 4; i++)
        #pragma unroll
        for (int j = 0; j < 4; j++)
            atomicAdd(&out[(4 * tg + i) * OUTD + 4 * to + j], acc[i][j]);
}

// -------------------- launch --------------------
extern "C" void kernel_launch(void* const* d_in, const int* in_sizes, int n_in,
                              void* d_out, int out_size) {
    const float* x   = (const float*)d_in[0];
    const void*  ei  = d_in[1];
    const float* W1  = (const float*)d_in[3];
    const float* b1  = (const float*)d_in[4];
    const float* W2  = (const float*)d_in[5];
    const float* b2  = (const float*)d_in[6];
    const float* W3  = (const float*)d_in[7];
    const float* b3  = (const float*)d_in[8];
    const float* Wfc = (const float*)d_in[9];
    const float* bfc = (const float*)d_in[10];
    float* out = (float*)d_out;

    // preprocessing
    detect_kernel<<<1, 1>>>(ei);
    zero_kernel<<<(NN + 255) / 256, 256>>>();
    hist_kernel<<<EE / 256, 256>>>(ei);
    reduce_kernel<<<NN / 256, 256>>>();
    scanpart_kernel<<<1, 256>>>();
    blockscan_kernel<<<NN / 256, 256>>>();
    scatter_kernel<<<EE / 256, 256>>>(ei);

    const int aggBlocks = (NN * 32) / 256;  // warp per node

    // layer 1: bufB = x @ W1 ; bufA = tanh(agg(bufB) + b1)
    gemm_kernel<F_IN, H1, -1, 1><<<dim3(H1 / 128, NN / 128), 256>>>(x, W1);
    agg_kernel<H1, 1, 0><<<aggBlocks, 256>>>(b1);

    // layer 2
    gemm_kernel<H1, H2, 0, 1><<<dim3(H2 / 128, NN / 128), 256>>>(nullptr, W2);
    agg_kernel<H2, 1, 0><<<aggBlocks, 256>>>(b2);

    // layer 3
    gemm_kernel<H2, H3, 0, 1><<<dim3(H3 / 128, NN / 128), 256>>>(nullptr, W3);
    agg_kernel<H3, 1, 0><<<aggBlocks, 256>>>(b3);

    // final FC with split-K atomics
    fc_init<<<(NG * OUTD + 255) / 256, 256>>>(bfc, out);
    fc_kernel<<<128000 / FC_KCH, 256>>>(Wfc, out);
}

// round 7
// speedup vs baseline: 1.4945x; 1.2573x over previous
#include <cuda_runtime.h>
#include <cuda_bf16.h>
#include <cstdint>
#include <cstddef>

// Problem constants (fixed by the dataset)
#define NN 64000
#define EE 1048576
#define NG 64
#define NBN 1000
#define F_IN 128
#define H1 256
#define H2 256
#define H3 128
#define OUTD 64

// -------------------- scratch (device globals; no allocs) --------------------
__device__ __align__(16) float g_bufA[(size_t)NN * 256];                 // fp32 h3 for FC
__device__ __align__(16) __nv_bfloat16 g_ahi[(size_t)NN * 256];          // GEMM A input hi
__device__ __align__(16) __nv_bfloat16 g_alo[(size_t)NN * 256];          // GEMM A input lo
__device__ __align__(16) __nv_bfloat16 g_bhi[(size_t)NN * 256];          // GEMM out / agg input hi
__device__ __align__(16) __nv_bfloat16 g_blo[(size_t)NN * 256];          // GEMM out / agg input lo
__device__ __align__(16) __nv_bfloat16 g_wtH[256 * 256];                 // W hi, [k][n]
__device__ __align__(16) __nv_bfloat16 g_wtL[256 * 256];                 // W lo, [k][n]
__device__ int   g_counts[NN];
__device__ int   g_offsets[NN + 1];
__device__ int   g_fill[NN];
__device__ int   g_srcSorted[EE];
__device__ float g_dinv[NN];
__device__ int   g_isI64;
__device__ int   g_bsum[256];
__device__ int   g_boff[256];

__device__ __forceinline__ int ei_at(const void* ei, size_t idx) {
    if (g_isI64) return (int)((const long long*)ei)[idx];
    return ((const int*)ei)[idx];
}

// -------------------- PTX helpers (family-generic sm_80+ features only) ------
__device__ __forceinline__ uint32_t smem_u32(const void* p) {
    uint32_t a;
    asm("{ .reg .u64 t; cvta.to.shared.u64 t, %1; cvt.u32.u64 %0, t; }" : "=r"(a) : "l"(p));
    return a;
}
#define LDSM_X4(r, a)                                                              \
    asm volatile("ldmatrix.sync.aligned.m8n8.x4.shared.b16 {%0,%1,%2,%3}, [%4];"   \
                 : "=r"((r)[0]), "=r"((r)[1]), "=r"((r)[2]), "=r"((r)[3]) : "r"(a))
#define LDSM_X4T(r, a)                                                                  \
    asm volatile("ldmatrix.sync.aligned.m8n8.x4.trans.shared.b16 {%0,%1,%2,%3}, [%4];"  \
                 : "=r"((r)[0]), "=r"((r)[1]), "=r"((r)[2]), "=r"((r)[3]) : "r"(a))

__device__ __forceinline__ void mma16816(float* c, const uint32_t* a,
                                         uint32_t b0, uint32_t b1) {
    asm volatile(
        "mma.sync.aligned.m16n8k16.row.col.f32.bf16.bf16.f32 "
        "{%0,%1,%2,%3}, {%4,%5,%6,%7}, {%8,%9}, {%0,%1,%2,%3};"
        : "+f"(c[0]), "+f"(c[1]), "+f"(c[2]), "+f"(c[3])
        : "r"(a[0]), "r"(a[1]), "r"(a[2]), "r"(a[3]), "r"(b0), "r"(b1));
}

// pack 2 floats -> bf16x2 (v0 in low half), and produce the lo-residual pack
__device__ __forceinline__ uint32_t pack_split(float v0, float v1, uint32_t& lopack) {
    uint32_t h;
    asm("cvt.rn.bf16x2.f32 %0, %1, %2;" : "=r"(h) : "f"(v1), "f"(v0));
    float h0 = __uint_as_float(h << 16);
    float h1 = __uint_as_float(h & 0xffff0000u);
    float l0 = v0 - h0, l1 = v1 - h1;
    asm("cvt.rn.bf16x2.f32 %0, %1, %2;" : "=r"(lopack) : "f"(l1), "f"(l0));
    return h;
}
// unpack bf16x2 u32 -> two floats
__device__ __forceinline__ void unpk(uint32_t u, float& f0, float& f1) {
    f0 = __uint_as_float(u << 16);
    f1 = __uint_as_float(u & 0xffff0000u);
}

// -------------------- dtype detection --------------------
__global__ void detect_kernel(const void* ei) {
    const unsigned int* w = (const unsigned int*)ei;
    int is64 = 1;
    #pragma unroll
    for (int i = 0; i < 32; i++)
        if (w[2 * i + 1] != 0u) is64 = 0;
    g_isI64 = is64;
}

// -------------------- preprocessing --------------------
__global__ void zero_kernel() {
    int i = blockIdx.x * blockDim.x + threadIdx.x;
    if (i < NN) { g_fill[i] = 0; g_counts[i] = 0; }
}

__global__ void hist_kernel(const void* __restrict__ ei) {
    int e = blockIdx.x * blockDim.x + threadIdx.x;
    if (e < EE) {
        int d = ei_at(ei, (size_t)EE + e);
        atomicAdd(&g_counts[d], 1);
    }
}

__global__ void reduce_kernel() {
    int b = blockIdx.x;
    int v = g_counts[b * 256 + threadIdx.x];
    #pragma unroll
    for (int o = 16; o; o >>= 1) v += __shfl_down_sync(0xffffffffu, v, o);
    __shared__ int ws[8];
    if ((threadIdx.x & 31) == 0) ws[threadIdx.x >> 5] = v;
    __syncthreads();
    if (threadIdx.x == 0) {
        int s = 0;
        #pragma unroll
        for (int i = 0; i < 8; i++) s += ws[i];
        g_bsum[b] = s;
    }
}

__global__ void scanpart_kernel() {
    int t = threadIdx.x;
    int v = (t < NN / 256) ? g_bsum[t] : 0;
    int lane = t & 31, w = t >> 5;
    int x = v;
    #pragma unroll
    for (int o = 1; o < 32; o <<= 1) {
        int y = __shfl_up_sync(0xffffffffu, x, o);
        if (lane >= o) x += y;
    }
    __shared__ int ws[8], wso[8];
    if (lane == 31) ws[w] = x;
    __syncthreads();
    if (t < 8) {
        int s = 0;
        for (int i = 0; i < t; i++) s += ws[i];
        wso[t] = s;
    }
    __syncthreads();
    int incl = x + wso[w];
    if (t < NN / 256) g_boff[t] = incl - v;
    if (t == 255) g_offsets[NN] = incl;
}

__global__ void blockscan_kernel() {
    int b = blockIdx.x, t = threadIdx.x, i = b * 256 + t;
    int c = g_counts[i];
    int lane = t & 31, w = t >> 5;
    int x = c;
    #pragma unroll
    for (int o = 1; o < 32; o <<= 1) {
        int y = __shfl_up_sync(0xffffffffu, x, o);
        if (lane >= o) x += y;
    }
    __shared__ int ws[8], wso[8];
    if (lane == 31) ws[w] = x;
    __syncthreads();
    if (t < 8) {
        int s = 0;
        for (int j = 0; j < t; j++) s += ws[j];
        wso[t] = s;
    }
    __syncthreads();
    g_offsets[i] = x - c + wso[w] + g_boff[b];
    g_dinv[i] = rsqrtf((float)(c + 1));
}

__global__ void scatter_kernel(const void* __restrict__ ei) {
    int e = blockIdx.x * blockDim.x + threadIdx.x;
    if (e < EE) {
        int d = ei_at(ei, (size_t)EE + e);
        int s = ei_at(ei, (size_t)e);
        int pos = g_offsets[d] + atomicAdd(&g_fill[d], 1);
        g_srcSorted[pos] = s;
    }
}

// -------------------- weight split: Whi/Wlo[k][n] (layout preserved) ---------
template <int K, int NOUT>
__global__ void splitw_kernel(const float* __restrict__ W) {
    int i = blockIdx.x * blockDim.x + threadIdx.x;
    if (i >= K * NOUT) return;
    float v = W[i];
    __nv_bfloat16 h = __float2bfloat16(v);
    g_wtH[i] = h;
    g_wtL[i] = __float2bfloat16(v - __bfloat162float(h));
}

// -------------------- agg1: fp32 input (x, H=128) -> split bf16 output -------
__global__ void agg1_kernel(const float* __restrict__ x) {
    int gw = (blockIdx.x * blockDim.x + threadIdx.x) >> 5;
    int lane = threadIdx.x & 31;
    if (gw >= NN) return;
    const int n = gw;
    const float dd = g_dinv[n];
    const float w0 = dd * dd;

    float4 acc = ((const float4*)(x + (size_t)n * F_IN))[lane];
    acc.x *= w0; acc.y *= w0; acc.z *= w0; acc.w *= w0;

    const int e0 = g_offsets[n], e1 = g_offsets[n + 1];
    for (int e = e0; e < e1; e++) {
        int s = g_srcSorted[e];
        float w = dd * g_dinv[s];
        float4 v = ((const float4*)(x + (size_t)s * F_IN))[lane];
        acc.x += w * v.x; acc.y += w * v.y; acc.z += w * v.z; acc.w += w * v.w;
    }

    uint32_t l0, l1;
    uint32_t h0 = pack_split(acc.x, acc.y, l0);
    uint32_t h1 = pack_split(acc.z, acc.w, l1);
    ((uint2*)(g_ahi + (size_t)n * F_IN))[lane] = make_uint2(h0, h1);
    ((uint2*)(g_alo + (size_t)n * F_IN))[lane] = make_uint2(l0, l1);
}

// -------------------- agg23: split bf16 input (H=256) -> split bf16 output ---
__global__ void agg23_kernel() {
    int gw = (blockIdx.x * blockDim.x + threadIdx.x) >> 5;
    int lane = threadIdx.x & 31;
    if (gw >= NN) return;
    const int n = gw;
    const float dd = g_dinv[n];
    const float w0 = dd * dd;

    float acc[8];
    {
        uint4 hv = ((const uint4*)(g_bhi + (size_t)n * 256))[lane];
        uint4 lv = ((const uint4*)(g_blo + (size_t)n * 256))[lane];
        float a, b, c, d;
        unpk(hv.x, a, b); unpk(lv.x, c, d); acc[0] = w0 * (a + c); acc[1] = w0 * (b + d);
        unpk(hv.y, a, b); unpk(lv.y, c, d); acc[2] = w0 * (a + c); acc[3] = w0 * (b + d);
        unpk(hv.z, a, b); unpk(lv.z, c, d); acc[4] = w0 * (a + c); acc[5] = w0 * (b + d);
        unpk(hv.w, a, b); unpk(lv.w, c, d); acc[6] = w0 * (a + c); acc[7] = w0 * (b + d);
    }

    const int e0 = g_offsets[n], e1 = g_offsets[n + 1];
    for (int e = e0; e < e1; e++) {
        int s = g_srcSorted[e];
        float w = dd * g_dinv[s];
        uint4 hv = ((const uint4*)(g_bhi + (size_t)s * 256))[lane];
        uint4 lv = ((const uint4*)(g_blo + (size_t)s * 256))[lane];
        float a, b, c, d;
        unpk(hv.x, a, b); unpk(lv.x, c, d); acc[0] += w * (a + c); acc[1] += w * (b + d);
        unpk(hv.y, a, b); unpk(lv.y, c, d); acc[2] += w * (a + c); acc[3] += w * (b + d);
        unpk(hv.z, a, b); unpk(lv.z, c, d); acc[4] += w * (a + c); acc[5] += w * (b + d);
        unpk(hv.w, a, b); unpk(lv.w, c, d); acc[6] += w * (a + c); acc[7] += w * (b + d);
    }

    uint4 ho, lo;
    ho.x = pack_split(acc[0], acc[1], lo.x);
    ho.y = pack_split(acc[2], acc[3], lo.y);
    ho.z = pack_split(acc[4], acc[5], lo.z);
    ho.w = pack_split(acc[6], acc[7], lo.w);
    ((uint4*)(g_ahi + (size_t)n * 256))[lane] = ho;
    ((uint4*)(g_alo + (size_t)n * 256))[lane] = lo;
}

// -------------------- GEMM via mma.sync (HMMA): C = A(split) @ W(split) ------
// CTA tile 128x128, 8 warps (4x2), warp tile 32x64, k-chunk 64.
// A: g_ahi/g_alo [M][K] bf16 row-major.  B: g_wtH/g_wtL [K][NB] bf16 row-major.
// Epilogue: v = tanh(acc + bias). SPLITOUT=1 -> g_bhi/g_blo; else fp32 g_bufA.
#define A_PITCH 144   // 64 bf16 = 128B + 16B pad (LDSM conflict-free)
#define B_PITCH 272   // 128 bf16 = 256B + 16B pad
#define SM_AH 0
#define SM_AL (128 * A_PITCH)
#define SM_BH (2 * 128 * A_PITCH)
#define SM_BL (2 * 128 * A_PITCH + 64 * B_PITCH)
#define SM_TOT (2 * 128 * A_PITCH + 2 * 64 * B_PITCH)

template <int K, int NB, int SPLITOUT>
__global__ void __launch_bounds__(256, 1)
gemm_mma(const float* __restrict__ bias) {
    extern __shared__ char sm[];
    const int t = threadIdx.x;
    const int warp = t >> 5, lane = t & 31;
    const int wm = warp >> 1, wn = warp & 1;
    const int m0 = blockIdx.y * 128, n0 = blockIdx.x * 128;

    float c[2][8][4];
    #pragma unroll
    for (int i = 0; i < 2; i++)
        #pragma unroll
        for (int j = 0; j < 8; j++)
            #pragma unroll
            for (int q = 0; q < 4; q++) c[i][j][q] = 0.0f;

    for (int ch = 0; ch < K / 64; ch++) {
        const int k0 = ch * 64;
        // A chunk: 128 rows x 64 bf16 (128B) hi+lo
        #pragma unroll
        for (int i = 0; i < 4; i++) {
            int idx = t + i * 256;
            int row = idx >> 3, seg = idx & 7;
            size_t gofs = ((size_t)(m0 + row) * K + k0) * 2 + seg * 16;
            *(uint4*)(sm + SM_AH + row * A_PITCH + seg * 16) =
                *(const uint4*)((const char*)g_ahi + gofs);
            *(uint4*)(sm + SM_AL + row * A_PITCH + seg * 16) =
                *(const uint4*)((const char*)g_alo + gofs);
        }
        // B chunk: 64 rows x 128 bf16 (256B) hi+lo
        #pragma unroll
        for (int i = 0; i < 4; i++) {
            int idx = t + i * 256;
            int row = idx >> 4, seg = idx & 15;
            size_t gofs = ((size_t)(k0 + row) * NB + n0) * 2 + seg * 16;
            *(uint4*)(sm + SM_BH + row * B_PITCH + seg * 16) =
                *(const uint4*)((const char*)g_wtH + gofs);
            *(uint4*)(sm + SM_BL + row * B_PITCH + seg * 16) =
                *(const uint4*)((const char*)g_wtL + gofs);
        }
        __syncthreads();

        #pragma unroll
        for (int k16 = 0; k16 < 4; k16++) {
            uint32_t ah[2][4], al[2][4];
            #pragma unroll
            for (int mt = 0; mt < 2; mt++) {
                int row = wm * 32 + mt * 16 + (lane & 15);
                int cb = k16 * 32 + ((lane >> 4) << 4);
                LDSM_X4(ah[mt], smem_u32(sm + SM_AH + row * A_PITCH + cb));
                LDSM_X4(al[mt], smem_u32(sm + SM_AL + row * A_PITCH + cb));
            }
            uint32_t bh[4][4], bl[4][4];
            #pragma unroll
            for (int np = 0; np < 4; np++) {
                int krow = k16 * 16 + (lane & 7) + (lane & 8);
                int cb = wn * 128 + np * 32 + ((lane >> 4) << 4);
                LDSM_X4T(bh[np], smem_u32(sm + SM_BH + krow * B_PITCH + cb));
                LDSM_X4T(bl[np], smem_u32(sm + SM_BL + krow * B_PITCH + cb));
            }
            #pragma unroll
            for (int mt = 0; mt < 2; mt++) {
                #pragma unroll
                for (int np = 0; np < 4; np++) {
                    mma16816(c[mt][np * 2],     ah[mt], bh[np][0], bh[np][1]);
                    mma16816(c[mt][np * 2],     al[mt], bh[np][0], bh[np][1]);
                    mma16816(c[mt][np * 2],     ah[mt], bl[np][0], bl[np][1]);
                    mma16816(c[mt][np * 2 + 1], ah[mt], bh[np][2], bh[np][3]);
                    mma16816(c[mt][np * 2 + 1], al[mt], bh[np][2], bh[np][3]);
                    mma16816(c[mt][np * 2 + 1], ah[mt], bl[np][2], bl[np][3]);
                }
            }
        }
        __syncthreads();
    }

    // epilogue: tanh(acc + bias) -> split bf16 or fp32
    const int g = lane >> 2, tq = lane & 3;
    #pragma unroll
    for (int mt = 0; mt < 2; mt++) {
        int row = m0 + wm * 32 + mt * 16 + g;
        #pragma unroll
        for (int n8 = 0; n8 < 8; n8++) {
            int col = n0 + wn * 64 + n8 * 8 + 2 * tq;
            float b0 = __ldg(bias + col), b1 = __ldg(bias + col + 1);
            float v0 = tanhf(c[mt][n8][0] + b0);
            float v1 = tanhf(c[mt][n8][1] + b1);
            float v2 = tanhf(c[mt][n8][2] + b0);
            float v3 = tanhf(c[mt][n8][3] + b1);
            if (SPLITOUT) {
                uint32_t lo0, lo1;
                uint32_t hi0 = pack_split(v0, v1, lo0);
                uint32_t hi1 = pack_split(v2, v3, lo1);
                *(uint32_t*)(g_bhi + (size_t)row * NB + col) = hi0;
                *(uint32_t*)(g_blo + (size_t)row * NB + col) = lo0;
                *(uint32_t*)(g_bhi + (size_t)(row + 8) * NB + col) = hi1;
                *(uint32_t*)(g_blo + (size_t)(row + 8) * NB + col) = lo1;
            } else {
                *(float2*)(g_bufA + (size_t)row * NB + col) = make_float2(v0, v1);
                *(float2*)(g_bufA + (size_t)(row + 8) * NB + col) = make_float2(v2, v3);
            }
        }
    }
}

// -------------------- final FC: out[64,64] = h3.reshape(64,128000) @ Wfc + bfc
__global__ void fc_init(const float* __restrict__ bfc, float* __restrict__ out) {
    int i = blockIdx.x * blockDim.x + threadIdx.x;
    if (i < NG * OUTD) out[i] = bfc[i & 63];
}

#define FC_KCH 1024
__global__ void fc_kernel(const float* __restrict__ Wfc,
                          float* __restrict__ out) {
    const float* __restrict__ h3 = g_bufA;
    __shared__ float Ws[16][64];
    __shared__ float Hs[64][17];
    const int t = threadIdx.x;
    const int tg = t & 15;
    const int to = t >> 4;
    float acc[4][4];
    #pragma unroll
    for (int i = 0; i < 4; i++)
        #pragma unroll
        for (int j = 0; j < 4; j++) acc[i][j] = 0.0f;

    const int kbase = blockIdx.x * FC_KCH;
    for (int kk0 = 0; kk0 < FC_KCH; kk0 += 16) {
        const int k0 = kbase + kk0;
        #pragma unroll
        for (int rr = 0; rr < 4; rr++) {
            int idx = t + rr * 256;
            int kr = idx >> 6, nn = idx & 63;
            Ws[kr][nn] = Wfc[(size_t)(k0 + kr) * OUTD + nn];
        }
        #pragma unroll
        for (int rr = 0; rr < 4; rr++) {
            int idx = t + rr * 256;
            int g = idx >> 4, kk = idx & 15;
            Hs[g][kk] = h3[(size_t)g * 128000 + k0 + kk];
        }
        __syncthreads();
        #pragma unroll
        for (int kk = 0; kk < 16; kk++) {
            float hv[4], wv[4];
            #pragma unroll
            for (int i = 0; i < 4; i++) hv[i] = Hs[4 * tg + i][kk];
            #pragma unroll
            for (int j = 0; j < 4; j++) wv[j] = Ws[kk][4 * to + j];
            #pragma unroll
            for (int i = 0; i < 4; i++)
                #pragma unroll
                for (int j = 0; j < 4; j++) acc[i][j] += hv[i] * wv[j];
        }
        __syncthreads();
    }
    #pragma unroll
    for (int i = 0; i < 4; i++)
        #pragma unroll
        for (int j = 0; j < 4; j++)
            atomicAdd(&out[(4 * tg + i) * OUTD + 4 * to + j], acc[i][j]);
}

// -------------------- launch --------------------
extern "C" void kernel_launch(void* const* d_in, const int* in_sizes, int n_in,
                              void* d_out, int out_size) {
    const float* x   = (const float*)d_in[0];
    const void*  ei  = d_in[1];
    const float* W1  = (const float*)d_in[3];
    const float* b1  = (const float*)d_in[4];
    const float* W2  = (const float*)d_in[5];
    const float* b2  = (const float*)d_in[6];
    const float* W3  = (const float*)d_in[7];
    const float* b3  = (const float*)d_in[8];
    const float* Wfc = (const float*)d_in[9];
    const float* bfc = (const float*)d_in[10];
    float* out = (float*)d_out;

    cudaFuncSetAttribute(gemm_mma<F_IN, H1, 1>, cudaFuncAttributeMaxDynamicSharedMemorySize, SM_TOT);
    cudaFuncSetAttribute(gemm_mma<H1, H2, 1>,   cudaFuncAttributeMaxDynamicSharedMemorySize, SM_TOT);
    cudaFuncSetAttribute(gemm_mma<H2, H3, 0>,   cudaFuncAttributeMaxDynamicSharedMemorySize, SM_TOT);

    // preprocessing
    detect_kernel<<<1, 1>>>(ei);
    zero_kernel<<<(NN + 255) / 256, 256>>>();
    hist_kernel<<<EE / 256, 256>>>(ei);
    reduce_kernel<<<NN / 256, 256>>>();
    scanpart_kernel<<<1, 256>>>();
    blockscan_kernel<<<NN / 256, 256>>>();
    scatter_kernel<<<EE / 256, 256>>>(ei);

    const int aggBlocks = (NN * 32) / 256;

    // layer 1: agg-first (Â x) then GEMM(128->256) with tanh+b1 epilogue
    splitw_kernel<F_IN, H1><<<(F_IN * H1 + 255) / 256, 256>>>(W1);
    agg1_kernel<<<aggBlocks, 256>>>(x);
    gemm_mma<F_IN, H1, 1><<<dim3(H1 / 128, NN / 128), 256, SM_TOT>>>(b1);

    // layer 2: agg (256) then GEMM(256->256)
    splitw_kernel<H1, H2><<<(H1 * H2 + 255) / 256, 256>>>(W2);
    agg23_kernel<<<aggBlocks, 256>>>();
    gemm_mma<H1, H2, 1><<<dim3(H2 / 128, NN / 128), 256, SM_TOT>>>(b2);

    // layer 3: agg (256) then GEMM(256->128), fp32 out for FC
    splitw_kernel<H2, H3><<<(H2 * H3 + 255) / 256, 256>>>(W3);
    agg23_kernel<<<aggBlocks, 256>>>();
    gemm_mma<H2, H3, 0><<<dim3(H3 / 128, NN / 128), 256, SM_TOT>>>(b3);

    // final FC with split-K atomics
    fc_init<<<(NG * OUTD + 255) / 256, 256>>>(bfc, out);
    fc_kernel<<<128000 / FC_KCH, 256>>>(Wfc, out);
}

// round 8
// speedup vs baseline: 1.6470x; 1.1020x over previous
#include <cuda_runtime.h>
#include <cuda_bf16.h>
#include <cuda_fp16.h>
#include <cstdint>
#include <cstddef>

// Problem constants (fixed by the dataset)
#define NN 64000
#define EE 1048576
#define NG 64
#define NBN 1000
#define F_IN 128
#define H1 256
#define H2 256
#define H3 128
#define OUTD 64

// -------------------- scratch (device globals; no allocs) --------------------
__device__ __align__(16) float g_bufA[(size_t)NN * 256];          // fp32 h3 for FC
__device__ __align__(16) __nv_bfloat16 g_ahi[(size_t)NN * 256];   // GEMM A hi
__device__ __align__(16) __nv_bfloat16 g_alo[(size_t)NN * 256];   // GEMM A lo
__device__ __align__(16) __half g_hf[(size_t)NN * 256];           // fp16 activations (gather)
__device__ __align__(16) __nv_bfloat16 g_wtH[256 * 256];          // W hi, [k][n]
__device__ __align__(16) __nv_bfloat16 g_wtL[256 * 256];          // W lo, [k][n]
__device__ int   g_counts[NN];
__device__ int   g_offsets[NN + 1];
__device__ int   g_fill[NN];
__device__ int   g_srcSorted[EE];
__device__ float g_dinv[NN];
__device__ int   g_isI64;
__device__ int   g_bsum[256];
__device__ int   g_boff[256];

__device__ __forceinline__ int ei_at(const void* ei, size_t idx) {
    if (g_isI64) return (int)((const long long*)ei)[idx];
    return ((const int*)ei)[idx];
}

// -------------------- PTX helpers (family-generic sm_80+ features only) ------
__device__ __forceinline__ uint32_t smem_u32(const void* p) {
    uint32_t a;
    asm("{ .reg .u64 t; cvta.to.shared.u64 t, %1; cvt.u32.u64 %0, t; }" : "=r"(a) : "l"(p));
    return a;
}
#define LDSM_X4(r, a)                                                              \
    asm volatile("ldmatrix.sync.aligned.m8n8.x4.shared.b16 {%0,%1,%2,%3}, [%4];"   \
                 : "=r"((r)[0]), "=r"((r)[1]), "=r"((r)[2]), "=r"((r)[3]) : "r"(a))
#define LDSM_X4T(r, a)                                                                  \
    asm volatile("ldmatrix.sync.aligned.m8n8.x4.trans.shared.b16 {%0,%1,%2,%3}, [%4];"  \
                 : "=r"((r)[0]), "=r"((r)[1]), "=r"((r)[2]), "=r"((r)[3]) : "r"(a))

__device__ __forceinline__ void mma16816(float* c, const uint32_t* a,
                                         uint32_t b0, uint32_t b1) {
    asm volatile(
        "mma.sync.aligned.m16n8k16.row.col.f32.bf16.bf16.f32 "
        "{%0,%1,%2,%3}, {%4,%5,%6,%7}, {%8,%9}, {%0,%1,%2,%3};"
        : "+f"(c[0]), "+f"(c[1]), "+f"(c[2]), "+f"(c[3])
        : "r"(a[0]), "r"(a[1]), "r"(a[2]), "r"(a[3]), "r"(b0), "r"(b1));
}

// pack 2 floats -> bf16x2 (v0 in low half), and produce the lo-residual pack
__device__ __forceinline__ uint32_t pack_split(float v0, float v1, uint32_t& lopack) {
    uint32_t h;
    asm("cvt.rn.bf16x2.f32 %0, %1, %2;" : "=r"(h) : "f"(v1), "f"(v0));
    float h0 = __uint_as_float(h << 16);
    float h1 = __uint_as_float(h & 0xffff0000u);
    float l0 = v0 - h0, l1 = v1 - h1;
    asm("cvt.rn.bf16x2.f32 %0, %1, %2;" : "=r"(lopack) : "f"(l1), "f"(l0));
    return h;
}
__device__ __forceinline__ float2 h2f2(uint32_t u) {
    return __half22float2(*(__half2*)&u);
}

// -------------------- dtype detection --------------------
__global__ void detect_kernel(const void* ei) {
    const unsigned int* w = (const unsigned int*)ei;
    int is64 = 1;
    #pragma unroll
    for (int i = 0; i < 32; i++)
        if (w[2 * i + 1] != 0u) is64 = 0;
    g_isI64 = is64;
}

// -------------------- preprocessing --------------------
__global__ void zero_kernel() {
    int i = blockIdx.x * blockDim.x + threadIdx.x;
    if (i < NN) { g_fill[i] = 0; g_counts[i] = 0; }
}

__global__ void hist_kernel(const void* __restrict__ ei) {
    int e = blockIdx.x * blockDim.x + threadIdx.x;
    if (e < EE) {
        int d = ei_at(ei, (size_t)EE + e);
        atomicAdd(&g_counts[d], 1);
    }
}

__global__ void reduce_kernel() {
    int b = blockIdx.x;
    int v = g_counts[b * 256 + threadIdx.x];
    #pragma unroll
    for (int o = 16; o; o >>= 1) v += __shfl_down_sync(0xffffffffu, v, o);
    __shared__ int ws[8];
    if ((threadIdx.x & 31) == 0) ws[threadIdx.x >> 5] = v;
    __syncthreads();
    if (threadIdx.x == 0) {
        int s = 0;
        #pragma unroll
        for (int i = 0; i < 8; i++) s += ws[i];
        g_bsum[b] = s;
    }
}

__global__ void scanpart_kernel() {
    int t = threadIdx.x;
    int v = (t < NN / 256) ? g_bsum[t] : 0;
    int lane = t & 31, w = t >> 5;
    int x = v;
    #pragma unroll
    for (int o = 1; o < 32; o <<= 1) {
        int y = __shfl_up_sync(0xffffffffu, x, o);
        if (lane >= o) x += y;
    }
    __shared__ int ws[8], wso[8];
    if (lane == 31) ws[w] = x;
    __syncthreads();
    if (t < 8) {
        int s = 0;
        for (int i = 0; i < t; i++) s += ws[i];
        wso[t] = s;
    }
    __syncthreads();
    int incl = x + wso[w];
    if (t < NN / 256) g_boff[t] = incl - v;
    if (t == 255) g_offsets[NN] = incl;
}

__global__ void blockscan_kernel() {
    int b = blockIdx.x, t = threadIdx.x, i = b * 256 + t;
    int c = g_counts[i];
    int lane = t & 31, w = t >> 5;
    int x = c;
    #pragma unroll
    for (int o = 1; o < 32; o <<= 1) {
        int y = __shfl_up_sync(0xffffffffu, x, o);
        if (lane >= o) x += y;
    }
    __shared__ int ws[8], wso[8];
    if (lane == 31) ws[w] = x;
    __syncthreads();
    if (t < 8) {
        int s = 0;
        for (int j = 0; j < t; j++) s += ws[j];
        wso[t] = s;
    }
    __syncthreads();
    g_offsets[i] = x - c + wso[w] + g_boff[b];
    g_dinv[i] = rsqrtf((float)(c + 1));
}

__global__ void scatter_kernel(const void* __restrict__ ei) {
    int e = blockIdx.x * blockDim.x + threadIdx.x;
    if (e < EE) {
        int d = ei_at(ei, (size_t)EE + e);
        int s = ei_at(ei, (size_t)e);
        int pos = g_offsets[d] + atomicAdd(&g_fill[d], 1);
        g_srcSorted[pos] = s;
    }
}

// -------------------- x -> fp16 --------------------
__global__ void xconv_kernel(const float* __restrict__ x) {
    int i = blockIdx.x * blockDim.x + threadIdx.x;  // over NN*F_IN/2
    if (i < NN * F_IN / 2) {
        float2 v = ((const float2*)x)[i];
        ((__half2*)g_hf)[i] = __floats2half2_rn(v.x, v.y);
    }
}

// -------------------- weight split: Whi/Wlo[k][n] (layout preserved) ---------
template <int K, int NOUT>
__global__ void splitw_kernel(const float* __restrict__ W) {
    int i = blockIdx.x * blockDim.x + threadIdx.x;
    if (i >= K * NOUT) return;
    float v = W[i];
    __nv_bfloat16 h = __float2bfloat16(v);
    g_wtH[i] = h;
    g_wtL[i] = __float2bfloat16(v - __bfloat162float(h));
}

// -------------------- agg1: fp16 x (H=128) -> split bf16 output --------------
__global__ void agg1_kernel() {
    int gw = (blockIdx.x * blockDim.x + threadIdx.x) >> 5;
    int lane = threadIdx.x & 31;
    if (gw >= NN) return;
    const int n = gw;
    const float dd = g_dinv[n];
    const float w0 = dd * dd;

    float acc[4];
    {
        uint2 hv = ((const uint2*)(g_hf + (size_t)n * F_IN))[lane];
        float2 f0 = h2f2(hv.x), f1 = h2f2(hv.y);
        acc[0] = w0 * f0.x; acc[1] = w0 * f0.y;
        acc[2] = w0 * f1.x; acc[3] = w0 * f1.y;
    }

    const int e0 = g_offsets[n], e1 = g_offsets[n + 1];
    for (int e = e0; e < e1; e++) {
        int s = g_srcSorted[e];
        float w = dd * g_dinv[s];
        uint2 hv = ((const uint2*)(g_hf + (size_t)s * F_IN))[lane];
        float2 f0 = h2f2(hv.x), f1 = h2f2(hv.y);
        acc[0] += w * f0.x; acc[1] += w * f0.y;
        acc[2] += w * f1.x; acc[3] += w * f1.y;
    }

    uint32_t l0, l1;
    uint32_t h0 = pack_split(acc[0], acc[1], l0);
    uint32_t h1 = pack_split(acc[2], acc[3], l1);
    ((uint2*)(g_ahi + (size_t)n * F_IN))[lane] = make_uint2(h0, h1);
    ((uint2*)(g_alo + (size_t)n * F_IN))[lane] = make_uint2(l0, l1);
}

// -------------------- agg23: fp16 input (H=256) -> split bf16 output ---------
__global__ void agg23_kernel() {
    int gw = (blockIdx.x * blockDim.x + threadIdx.x) >> 5;
    int lane = threadIdx.x & 31;
    if (gw >= NN) return;
    const int n = gw;
    const float dd = g_dinv[n];
    const float w0 = dd * dd;

    float acc[8];
    {
        uint4 hv = ((const uint4*)(g_hf + (size_t)n * 256))[lane];
        float2 f0 = h2f2(hv.x), f1 = h2f2(hv.y), f2 = h2f2(hv.z), f3 = h2f2(hv.w);
        acc[0] = w0 * f0.x; acc[1] = w0 * f0.y; acc[2] = w0 * f1.x; acc[3] = w0 * f1.y;
        acc[4] = w0 * f2.x; acc[5] = w0 * f2.y; acc[6] = w0 * f3.x; acc[7] = w0 * f3.y;
    }

    const int e0 = g_offsets[n], e1 = g_offsets[n + 1];
    for (int e = e0; e < e1; e++) {
        int s = g_srcSorted[e];
        float w = dd * g_dinv[s];
        uint4 hv = ((const uint4*)(g_hf + (size_t)s * 256))[lane];
        float2 f0 = h2f2(hv.x), f1 = h2f2(hv.y), f2 = h2f2(hv.z), f3 = h2f2(hv.w);
        acc[0] += w * f0.x; acc[1] += w * f0.y; acc[2] += w * f1.x; acc[3] += w * f1.y;
        acc[4] += w * f2.x; acc[5] += w * f2.y; acc[6] += w * f3.x; acc[7] += w * f3.y;
    }

    uint4 ho, lo;
    ho.x = pack_split(acc[0], acc[1], lo.x);
    ho.y = pack_split(acc[2], acc[3], lo.y);
    ho.z = pack_split(acc[4], acc[5], lo.z);
    ho.w = pack_split(acc[6], acc[7], lo.w);
    ((uint4*)(g_ahi + (size_t)n * 256))[lane] = ho;
    ((uint4*)(g_alo + (size_t)n * 256))[lane] = lo;
}

// -------------------- GEMM via mma.sync (HMMA): C = A(split) @ W(split) ------
// CTA tile 128x128, 8 warps (4x2), warp tile 32x64, k-chunk 64.
// Epilogue: v = tanh(acc + bias). HALFOUT=1 -> g_hf fp16; else fp32 g_bufA.
#define A_PITCH 144   // 64 bf16 = 128B + 16B pad
#define B_PITCH 272   // 128 bf16 = 256B + 16B pad
#define SM_AH 0
#define SM_AL (128 * A_PITCH)
#define SM_BH (2 * 128 * A_PITCH)
#define SM_BL (2 * 128 * A_PITCH + 64 * B_PITCH)
#define SM_TOT (2 * 128 * A_PITCH + 2 * 64 * B_PITCH)

template <int K, int NB, int HALFOUT>
__global__ void __launch_bounds__(256, 1)
gemm_mma(const float* __restrict__ bias) {
    extern __shared__ char sm[];
    const int t = threadIdx.x;
    const int warp = t >> 5, lane = t & 31;
    const int wm = warp >> 1, wn = warp & 1;
    const int m0 = blockIdx.y * 128, n0 = blockIdx.x * 128;

    float c[2][8][4];
    #pragma unroll
    for (int i = 0; i < 2; i++)
        #pragma unroll
        for (int j = 0; j < 8; j++)
            #pragma unroll
            for (int q = 0; q < 4; q++) c[i][j][q] = 0.0f;

    for (int ch = 0; ch < K / 64; ch++) {
        const int k0 = ch * 64;
        #pragma unroll
        for (int i = 0; i < 4; i++) {
            int idx = t + i * 256;
            int row = idx >> 3, seg = idx & 7;
            size_t gofs = ((size_t)(m0 + row) * K + k0) * 2 + seg * 16;
            *(uint4*)(sm + SM_AH + row * A_PITCH + seg * 16) =
                *(const uint4*)((const char*)g_ahi + gofs);
            *(uint4*)(sm + SM_AL + row * A_PITCH + seg * 16) =
                *(const uint4*)((const char*)g_alo + gofs);
        }
        #pragma unroll
        for (int i = 0; i < 4; i++) {
            int idx = t + i * 256;
            int row = idx >> 4, seg = idx & 15;
            size_t gofs = ((size_t)(k0 + row) * NB + n0) * 2 + seg * 16;
            *(uint4*)(sm + SM_BH + row * B_PITCH + seg * 16) =
                *(const uint4*)((const char*)g_wtH + gofs);
            *(uint4*)(sm + SM_BL + row * B_PITCH + seg * 16) =
                *(const uint4*)((const char*)g_wtL + gofs);
        }
        __syncthreads();

        #pragma unroll
        for (int k16 = 0; k16 < 4; k16++) {
            uint32_t ah[2][4], al[2][4];
            #pragma unroll
            for (int mt = 0; mt < 2; mt++) {
                int row = wm * 32 + mt * 16 + (lane & 15);
                int cb = k16 * 32 + ((lane >> 4) << 4);
                LDSM_X4(ah[mt], smem_u32(sm + SM_AH + row * A_PITCH + cb));
                LDSM_X4(al[mt], smem_u32(sm + SM_AL + row * A_PITCH + cb));
            }
            uint32_t bh[4][4], bl[4][4];
            #pragma unroll
            for (int np = 0; np < 4; np++) {
                int krow = k16 * 16 + (lane & 7) + (lane & 8);
                int cb = wn * 128 + np * 32 + ((lane >> 4) << 4);
                LDSM_X4T(bh[np], smem_u32(sm + SM_BH + krow * B_PITCH + cb));
                LDSM_X4T(bl[np], smem_u32(sm + SM_BL + krow * B_PITCH + cb));
            }
            #pragma unroll
            for (int mt = 0; mt < 2; mt++) {
                #pragma unroll
                for (int np = 0; np < 4; np++) {
                    mma16816(c[mt][np * 2],     ah[mt], bh[np][0], bh[np][1]);
                    mma16816(c[mt][np * 2],     al[mt], bh[np][0], bh[np][1]);
                    mma16816(c[mt][np * 2],     ah[mt], bl[np][0], bl[np][1]);
                    mma16816(c[mt][np * 2 + 1], ah[mt], bh[np][2], bh[np][3]);
                    mma16816(c[mt][np * 2 + 1], al[mt], bh[np][2], bh[np][3]);
                    mma16816(c[mt][np * 2 + 1], ah[mt], bl[np][2], bl[np][3]);
                }
            }
        }
        __syncthreads();
    }

    // epilogue: tanh(acc + bias) -> fp16 (for gather) or fp32 (for FC)
    const int g = lane >> 2, tq = lane & 3;
    #pragma unroll
    for (int mt = 0; mt < 2; mt++) {
        int row = m0 + wm * 32 + mt * 16 + g;
        #pragma unroll
        for (int n8 = 0; n8 < 8; n8++) {
            int col = n0 + wn * 64 + n8 * 8 + 2 * tq;
            float b0 = __ldg(bias + col), b1 = __ldg(bias + col + 1);
            float v0 = tanhf(c[mt][n8][0] + b0);
            float v1 = tanhf(c[mt][n8][1] + b1);
            float v2 = tanhf(c[mt][n8][2] + b0);
            float v3 = tanhf(c[mt][n8][3] + b1);
            if (HALFOUT) {
                *(__half2*)(g_hf + (size_t)row * NB + col) = __floats2half2_rn(v0, v1);
                *(__half2*)(g_hf + (size_t)(row + 8) * NB + col) = __floats2half2_rn(v2, v3);
            } else {
                *(float2*)(g_bufA + (size_t)row * NB + col) = make_float2(v0, v1);
                *(float2*)(g_bufA + (size_t)(row + 8) * NB + col) = make_float2(v2, v3);
            }
        }
    }
}

// -------------------- final FC: out[64,64] = h3.reshape(64,128000) @ Wfc + bfc
__global__ void fc_init(const float* __restrict__ bfc, float* __restrict__ out) {
    int i = blockIdx.x * blockDim.x + threadIdx.x;
    if (i < NG * OUTD) out[i] = bfc[i & 63];
}

#define FC_KCH 1024
__global__ void fc_kernel(const float* __restrict__ Wfc,
                          float* __restrict__ out) {
    const float* __restrict__ h3 = g_bufA;
    __shared__ float Ws[16][64];
    __shared__ float Hs[64][17];
    const int t = threadIdx.x;
    const int tg = t & 15;
    const int to = t >> 4;
    float acc[4][4];
    #pragma unroll
    for (int i = 0; i < 4; i++)
        #pragma unroll
        for (int j = 0; j < 4; j++) acc[i][j] = 0.0f;

    const int kbase = blockIdx.x * FC_KCH;
    for (int kk0 = 0; kk0 < FC_KCH; kk0 += 16) {
        const int k0 = kbase + kk0;
        #pragma unroll
        for (int rr = 0; rr < 4; rr++) {
            int idx = t + rr * 256;
            int kr = idx >> 6, nn = idx & 63;
            Ws[kr][nn] = Wfc[(size_t)(k0 + kr) * OUTD + nn];
        }
        #pragma unroll
        for (int rr = 0; rr < 4; rr++) {
            int idx = t + rr * 256;
            int g = idx >> 4, kk = idx & 15;
            Hs[g][kk] = h3[(size_t)g * 128000 + k0 + kk];
        }
        __syncthreads();
        #pragma unroll
        for (int kk = 0; kk < 16; kk++) {
            float hv[4], wv[4];
            #pragma unroll
            for (int i = 0; i < 4; i++) hv[i] = Hs[4 * tg + i][kk];
            #pragma unroll
            for (int j = 0; j < 4; j++) wv[j] = Ws[kk][4 * to + j];
            #pragma unroll
            for (int i = 0; i < 4; i++)
                #pragma unroll
                for (int j = 0; j < 4; j++) acc[i][j] += hv[i] * wv[j];
        }
        __syncthreads();
    }
    #pragma unroll
    for (int i = 0; i < 4; i++)
        #pragma unroll
        for (int j = 0; j < 4; j++)
            atomicAdd(&out[(4 * tg + i) * OUTD + 4 * to + j], acc[i][j]);
}

// -------------------- launch --------------------
extern "C" void kernel_launch(void* const* d_in, const int* in_sizes, int n_in,
                              void* d_out, int out_size) {
    const float* x   = (const float*)d_in[0];
    const void*  ei  = d_in[1];
    const float* W1  = (const float*)d_in[3];
    const float* b1  = (const float*)d_in[4];
    const float* W2  = (const float*)d_in[5];
    const float* b2  = (const float*)d_in[6];
    const float* W3  = (const float*)d_in[7];
    const float* b3  = (const float*)d_in[8];
    const float* Wfc = (const float*)d_in[9];
    const float* bfc = (const float*)d_in[10];
    float* out = (float*)d_out;

    cudaFuncSetAttribute(gemm_mma<F_IN, H1, 1>, cudaFuncAttributeMaxDynamicSharedMemorySize, SM_TOT);
    cudaFuncSetAttribute(gemm_mma<H1, H2, 1>,   cudaFuncAttributeMaxDynamicSharedMemorySize, SM_TOT);
    cudaFuncSetAttribute(gemm_mma<H2, H3, 0>,   cudaFuncAttributeMaxDynamicSharedMemorySize, SM_TOT);

    // preprocessing
    detect_kernel<<<1, 1>>>(ei);
    zero_kernel<<<(NN + 255) / 256, 256>>>();
    hist_kernel<<<EE / 256, 256>>>(ei);
    reduce_kernel<<<NN / 256, 256>>>();
    scanpart_kernel<<<1, 256>>>();
    blockscan_kernel<<<NN / 256, 256>>>();
    scatter_kernel<<<EE / 256, 256>>>(ei);
    xconv_kernel<<<(NN * F_IN / 2 + 255) / 256, 256>>>(x);

    const int aggBlocks = (NN * 32) / 256;

    // layer 1: agg-first (Â x, fp16 gather) then GEMM(128->256), tanh -> fp16
    splitw_kernel<F_IN, H1><<<(F_IN * H1 + 255) / 256, 256>>>(W1);
    agg1_kernel<<<aggBlocks, 256>>>();
    gemm_mma<F_IN, H1, 1><<<dim3(H1 / 128, NN / 128), 256, SM_TOT>>>(b1);

    // layer 2: agg (fp16 gather, 256) then GEMM(256->256), tanh -> fp16
    splitw_kernel<H1, H2><<<(H1 * H2 + 255) / 256, 256>>>(W2);
    agg23_kernel<<<aggBlocks, 256>>>();
    gemm_mma<H1, H2, 1><<<dim3(H2 / 128, NN / 128), 256, SM_TOT>>>(b2);

    // layer 3: agg then GEMM(256->128), tanh -> fp32 for FC
    splitw_kernel<H2, H3><<<(H2 * H3 + 255) / 256, 256>>>(W3);
    agg23_kernel<<<aggBlocks, 256>>>();
    gemm_mma<H2, H3, 0><<<dim3(H3 / 128, NN / 128), 256, SM_TOT>>>(b3);

    // final FC with split-K atomics
    fc_init<<<(NG * OUTD + 255) / 256, 256>>>(bfc, out);
    fc_kernel<<<128000 / FC_KCH, 256>>>(Wfc, out);
}